// round 1
// baseline (speedup 1.0000x reference)
#include <cuda_runtime.h>
#include <math.h>

// Problem constants
#define LL    6
#define BSZ   8
#define FCH   32
#define MAPD  125
#define LOCD  25
#define NA    8
#define NPIX  (MAPD*MAPD)   // 15625
#define KSZ   (LOCD*LOCD)   // 625

// Conv tiling
#define TY    7
#define NYT   18            // ceil(125/7)
#define TROWS 31            // TY + 24
#define TCOLS 152           // 125 + 24 halo, padded to 152

// Scratch (device globals; no allocation allowed)
__device__ float g_rot[LL*BSZ*NA*FCH*KSZ];     // 7,680,000 rotated tiles [l][b][a][f][25][25]
__device__ float g_p0[BSZ*NA*NPIX];            // initial pose belief
__device__ float g_oreg[BSZ*FCH*NPIX];         // conv1 output (GRU input)
__device__ float g_msm[BSZ*(FCH-1)*NPIX];      // channel-softmaxed maps, ch 1..31
__device__ float g_scores[BSZ*NA*NPIX];        // conv2 output (pre-softmax)

// ---------------------------------------------------------------------------
// Rotation resample: image_cls (L,BS,F,25,25) -> g_rot (L,BS,A,F,25,25)
// bilinear, zero padding; matches jax affine_grid-style sampling
// ---------------------------------------------------------------------------
__global__ void resample_kernel(const float* __restrict__ img)
{
    int idx = blockIdx.x * blockDim.x + threadIdx.x;
    const int total = LL*BSZ*NA*FCH*KSZ;
    if (idx >= total) return;

    int xx = idx % LOCD;
    int yy = (idx / LOCD) % LOCD;
    int f  = (idx / KSZ) % FCH;
    int a  = (idx / (KSZ*FCH)) % NA;
    int lb = idx / (KSZ*FCH*NA);          // l*BSZ + b

    float gx = -1.0f + (float)xx * (2.0f/24.0f);
    float gy = -1.0f + (float)yy * (2.0f/24.0f);
    float ang = (float)a * 0.78539816339744830961f;
    float sn, c;
    sincosf(ang, &sn, &c);
    float px = (c*gx - sn*gy + 1.0f) * 12.0f;   // column coord
    float py = (sn*gx + c*gy + 1.0f) * 12.0f;   // row coord

    int x0 = (int)floorf(px);
    int y0 = (int)floorf(py);
    float wx1 = px - (float)x0, wy1 = py - (float)y0;
    float wx0 = 1.0f - wx1,     wy0 = 1.0f - wy1;

    const float* im = img + (lb*FCH + f)*KSZ;
    float v00 = (y0   >= 0 && y0   < LOCD && x0   >= 0 && x0   < LOCD) ? im[y0*LOCD + x0]       : 0.0f;
    float v01 = (y0   >= 0 && y0   < LOCD && x0+1 >= 0 && x0+1 < LOCD) ? im[y0*LOCD + x0+1]     : 0.0f;
    float v10 = (y0+1 >= 0 && y0+1 < LOCD && x0   >= 0 && x0   < LOCD) ? im[(y0+1)*LOCD + x0]   : 0.0f;
    float v11 = (y0+1 >= 0 && y0+1 < LOCD && x0+1 >= 0 && x0+1 < LOCD) ? im[(y0+1)*LOCD + x0+1] : 0.0f;

    g_rot[idx] = v00*wy0*wx0 + v01*wy0*wx1 + v10*wy1*wx0 + v11*wy1*wx1;
}

// ---------------------------------------------------------------------------
// p0 init: zeros except p0[b][0][62][62] = 1
// ---------------------------------------------------------------------------
__global__ void p0_init_kernel()
{
    int i = blockIdx.x * blockDim.x + threadIdx.x;
    if (i < BSZ*NA*NPIX)
        g_p0[i] = ((i % (NA*NPIX)) == (62*MAPD + 62)) ? 1.0f : 0.0f;
}

// ---------------------------------------------------------------------------
// conv1 (write-memory): o_reg[b,f,y,x] = sum_{a,j,i} rot[t,b,a,f,j,i] * p[b,a,y+12-j,x+12-i]
// block = (ytile, co-group of 8, b); 128 threads over x
// ---------------------------------------------------------------------------
__global__ __launch_bounds__(128)
void conv1_kernel(int t, const float* __restrict__ psrc)
{
    __shared__ float wts[8*KSZ];        // 20 KB
    __shared__ float pt[TROWS*TCOLS];   // 18.8 KB

    const int tid = threadIdx.x;
    const int yt  = blockIdx.x;
    const int cg  = blockIdx.y;         // 0..3, 8 out-ch each
    const int b   = blockIdx.z;
    const int y0  = yt * TY;

    const float* p     = psrc ? psrc : g_p0;
    const float* rot_t = g_rot + t * (BSZ*NA*FCH*KSZ);

    float acc[TY][8];
#pragma unroll
    for (int r = 0; r < TY; r++)
#pragma unroll
        for (int co = 0; co < 8; co++) acc[r][co] = 0.0f;

    for (int a = 0; a < NA; a++) {
        __syncthreads();
        // load padded p tile (zeros outside)
        const float* ps = p + (b*NA + a)*NPIX;
        for (int i = tid; i < TROWS*TCOLS; i += 128) {
            int rr = i / TCOLS, cc = i % TCOLS;
            int gy = y0 + rr - 12, gx = cc - 12;
            pt[i] = (gy >= 0 && gy < MAPD && gx >= 0 && gx < MAPD) ? ps[gy*MAPD + gx] : 0.0f;
        }
        // load weights for this (a, co-group)
        const float* ws = rot_t + ((b*NA + a)*FCH + cg*8)*KSZ;
        for (int i = tid; i < 8*KSZ; i += 128) wts[i] = ws[i];
        __syncthreads();

        if (tid < MAPD) {
            for (int j = 0; j < LOCD; j++) {
                int pbase = (24 - j)*TCOLS + tid + 24;
                int wbase = j*LOCD;
#pragma unroll 5
                for (int i = 0; i < LOCD; i++) {
                    float pv[TY];
#pragma unroll
                    for (int r = 0; r < TY; r++) pv[r] = pt[pbase + r*TCOLS - i];
#pragma unroll
                    for (int co = 0; co < 8; co++) {
                        float w = wts[co*KSZ + wbase + i];
#pragma unroll
                        for (int r = 0; r < TY; r++)
                            acc[r][co] = fmaf(pv[r], w, acc[r][co]);
                    }
                }
            }
        }
    }

    if (tid < MAPD) {
#pragma unroll
        for (int co = 0; co < 8; co++)
#pragma unroll
            for (int r = 0; r < TY; r++) {
                int y = y0 + r;
                if (y < MAPD)
                    g_oreg[(b*FCH + cg*8 + co)*NPIX + y*MAPD + tid] = acc[r][co];
            }
    }
}

// ---------------------------------------------------------------------------
// GRU cell per pixel + channel softmax.
// x = g_oreg, h = hprev; writes m to mout (maps_all slot / next-step h)
// and softmaxed channels 1..31 to g_msm.
// ---------------------------------------------------------------------------
__global__ __launch_bounds__(128)
void gru_kernel(const float* __restrict__ hprev,
                const float* __restrict__ w_ih, const float* __restrict__ w_hh,
                const float* __restrict__ b_ih, const float* __restrict__ b_hh,
                float* __restrict__ mout)
{
    __shared__ float4 s_wih[96*8];
    __shared__ float4 s_whh[96*8];
    __shared__ float  s_b[192];

    const int tid = threadIdx.x;
    const float4* wi4 = (const float4*)w_ih;
    const float4* wh4 = (const float4*)w_hh;
    for (int i = tid; i < 96*8; i += 128) { s_wih[i] = wi4[i]; s_whh[i] = wh4[i]; }
    if (tid < 96) { s_b[tid] = b_ih[tid]; s_b[96+tid] = b_hh[tid]; }
    __syncthreads();

    const int pix = blockIdx.x * 128 + tid;
    if (pix >= NPIX) return;
    const int b = blockIdx.y;

    float x[32], h[32];
#pragma unroll
    for (int c = 0; c < 32; c++) {
        x[c] = g_oreg[(b*FCH + c)*NPIX + pix];
        h[c] = hprev[(b*FCH + c)*NPIX + pix];
    }

    float mx = -1e30f;
    for (int c = 0; c < 32; c++) {
        float accr = s_b[c]      + s_b[96+c];
        float accz = s_b[32+c]   + s_b[128+c];
        float acci = s_b[64+c];
        float acch = s_b[160+c];
        const float4* wr_i = s_wih + c*8;
        const float4* wz_i = s_wih + (32+c)*8;
        const float4* wn_i = s_wih + (64+c)*8;
        const float4* wr_h = s_whh + c*8;
        const float4* wz_h = s_whh + (32+c)*8;
        const float4* wn_h = s_whh + (64+c)*8;
#pragma unroll
        for (int k = 0; k < 8; k++) {
            float4 wv;
            wv = wr_i[k]; accr += wv.x*x[4*k] + wv.y*x[4*k+1] + wv.z*x[4*k+2] + wv.w*x[4*k+3];
            wv = wr_h[k]; accr += wv.x*h[4*k] + wv.y*h[4*k+1] + wv.z*h[4*k+2] + wv.w*h[4*k+3];
            wv = wz_i[k]; accz += wv.x*x[4*k] + wv.y*x[4*k+1] + wv.z*x[4*k+2] + wv.w*x[4*k+3];
            wv = wz_h[k]; accz += wv.x*h[4*k] + wv.y*h[4*k+1] + wv.z*h[4*k+2] + wv.w*h[4*k+3];
            wv = wn_i[k]; acci += wv.x*x[4*k] + wv.y*x[4*k+1] + wv.z*x[4*k+2] + wv.w*x[4*k+3];
            wv = wn_h[k]; acch += wv.x*h[4*k] + wv.y*h[4*k+1] + wv.z*h[4*k+2] + wv.w*h[4*k+3];
        }
        float r = 1.0f/(1.0f + expf(-accr));
        float z = 1.0f/(1.0f + expf(-accz));
        float n = tanhf(acci + r*acch);
        float hc = hprev[(b*FCH + c)*NPIX + pix];
        float mv = (1.0f - z)*n + z*hc;
        mout[(b*FCH + c)*NPIX + pix] = mv;
        mx = fmaxf(mx, mv);
    }

    // channel softmax (GRU_SCALAR = 1); denominator includes channel 0
    float sum = 0.0f;
    for (int c = 0; c < 32; c++) {
        float mv = mout[(b*FCH + c)*NPIX + pix];
        float e = expf(mv - mx);
        sum += e;
        if (c >= 1) g_msm[(b*(FCH-1) + (c-1))*NPIX + pix] = e;
    }
    float inv = 1.0f / sum;
    for (int c = 0; c < FCH-1; c++)
        g_msm[(b*(FCH-1) + c)*NPIX + pix] *= inv;
}

// ---------------------------------------------------------------------------
// conv2 (localize): scores[b,a,y,x] = sum_{c=0..30,ky,kx}
//    msm[b,c,y+ky-12,x+kx-12] * rot[t+1,b,a,c+1,ky,kx]
// block = (ytile, b); 128 threads over x; all 8 output angles per block
// ---------------------------------------------------------------------------
__global__ __launch_bounds__(128)
void conv2_kernel(int t)
{
    __shared__ float wts[8*KSZ];        // 20 KB (8 angles, one input channel)
    __shared__ float pt[TROWS*TCOLS];   // 18.8 KB

    const int tid = threadIdx.x;
    const int yt  = blockIdx.x;
    const int b   = blockIdx.y;
    const int y0  = yt * TY;
    const float* rot_n = g_rot + (t+1) * (BSZ*NA*FCH*KSZ);

    float acc[TY][8];
#pragma unroll
    for (int r = 0; r < TY; r++)
#pragma unroll
        for (int a = 0; a < 8; a++) acc[r][a] = 0.0f;

    for (int c = 0; c < FCH-1; c++) {
        __syncthreads();
        const float* ps = g_msm + (b*(FCH-1) + c)*NPIX;
        for (int i = tid; i < TROWS*TCOLS; i += 128) {
            int rr = i / TCOLS, cc = i % TCOLS;
            int gy = y0 + rr - 12, gx = cc - 12;
            pt[i] = (gy >= 0 && gy < MAPD && gx >= 0 && gx < MAPD) ? ps[gy*MAPD + gx] : 0.0f;
        }
        for (int i = tid; i < 8*KSZ; i += 128) {
            int a = i / KSZ, k = i % KSZ;
            wts[i] = rot_n[((b*NA + a)*FCH + (c+1))*KSZ + k];
        }
        __syncthreads();

        if (tid < MAPD) {
            for (int ky = 0; ky < LOCD; ky++) {
                int pbase = ky*TCOLS + tid;
                int wbase = ky*LOCD;
#pragma unroll 5
                for (int kx = 0; kx < LOCD; kx++) {
                    float pv[TY];
#pragma unroll
                    for (int r = 0; r < TY; r++) pv[r] = pt[pbase + r*TCOLS + kx];
#pragma unroll
                    for (int a = 0; a < 8; a++) {
                        float w = wts[a*KSZ + wbase + kx];
#pragma unroll
                        for (int r = 0; r < TY; r++)
                            acc[r][a] = fmaf(pv[r], w, acc[r][a]);
                    }
                }
            }
        }
    }

    if (tid < MAPD) {
#pragma unroll
        for (int a = 0; a < 8; a++)
#pragma unroll
            for (int r = 0; r < TY; r++) {
                int y = y0 + r;
                if (y < MAPD)
                    g_scores[(b*NA + a)*NPIX + y*MAPD + tid] = acc[r][a];
            }
    }
}

// ---------------------------------------------------------------------------
// Global softmax over (A,H,W) = 125000 per batch. 1 block/batch, 1024 threads.
// ---------------------------------------------------------------------------
__global__ void softmax_pose_kernel(float* __restrict__ pdst)
{
    const int b = blockIdx.x;
    const float* s = g_scores + b*NA*NPIX;
    float* o = pdst + b*NA*NPIX;
    const int N = NA*NPIX;
    __shared__ float red[33];
    const int tid = threadIdx.x;

    float mx = -1e30f;
    for (int i = tid; i < N; i += 1024) mx = fmaxf(mx, s[i]);
#pragma unroll
    for (int off = 16; off; off >>= 1) mx = fmaxf(mx, __shfl_xor_sync(0xffffffffu, mx, off));
    if ((tid & 31) == 0) red[tid >> 5] = mx;
    __syncthreads();
    if (tid < 32) {
        float v = red[tid];
#pragma unroll
        for (int off = 16; off; off >>= 1) v = fmaxf(v, __shfl_xor_sync(0xffffffffu, v, off));
        if (tid == 0) red[32] = v;
    }
    __syncthreads();
    mx = red[32];
    __syncthreads();

    float sum = 0.0f;
    for (int i = tid; i < N; i += 1024) sum += expf(s[i] - mx);
#pragma unroll
    for (int off = 16; off; off >>= 1) sum += __shfl_xor_sync(0xffffffffu, sum, off);
    if ((tid & 31) == 0) red[tid >> 5] = sum;
    __syncthreads();
    if (tid < 32) {
        float v = red[tid];
#pragma unroll
        for (int off = 16; off; off >>= 1) v += __shfl_xor_sync(0xffffffffu, v, off);
        if (tid == 0) red[32] = v;
    }
    __syncthreads();
    float inv = 1.0f / red[32];

    for (int i = tid; i < N; i += 1024) o[i] = expf(s[i] - mx) * inv;
}

// ---------------------------------------------------------------------------
// Host launcher: graph-capturable, allocation-free.
// Output layout: poses_all (5,8,8,125,125) | maps_all (5,8,32,125,125) | m_final (8,32,125,125)
// Recurrent state lives in the output slots themselves.
// ---------------------------------------------------------------------------
extern "C" void kernel_launch(void* const* d_in, const int* in_sizes, int n_in,
                              void* d_out, int out_size)
{
    const float* img   = (const float*)d_in[0];
    const float* maps0 = (const float*)d_in[1];
    const float* w_ih  = (const float*)d_in[3];
    const float* w_hh  = (const float*)d_in[4];
    const float* b_ih  = (const float*)d_in[5];
    const float* b_hh  = (const float*)d_in[6];

    float* out   = (float*)d_out;
    float* poses = out;                                      // 5*8*8*15625   = 5,000,000
    float* mapso = out + 5*BSZ*NA*NPIX;                      // 5*8*32*15625  = 20,000,000
    float* mfin  = out + 5*BSZ*NA*NPIX + 5*BSZ*FCH*NPIX;     // 8*32*15625    = 4,000,000

    resample_kernel<<<(LL*BSZ*NA*FCH*KSZ + 255)/256, 256>>>(img);
    p0_init_kernel<<<(BSZ*NA*NPIX + 255)/256, 256>>>();

    for (int t = 0; t < LL-1; t++) {
        const float* psrc = (t == 0) ? nullptr : (poses + (t-1)*BSZ*NA*NPIX);
        const float* hsrc = (t == 0) ? maps0   : (mapso + (t-1)*BSZ*FCH*NPIX);
        float* mdst = mapso + t*BSZ*FCH*NPIX;
        float* pdst = poses + t*BSZ*NA*NPIX;

        conv1_kernel<<<dim3(NYT, 4, BSZ), 128>>>(t, psrc);
        gru_kernel<<<dim3((NPIX + 127)/128, BSZ), 128>>>(hsrc, w_ih, w_hh, b_ih, b_hh, mdst);
        conv2_kernel<<<dim3(NYT, BSZ), 128>>>(t);
        softmax_pose_kernel<<<BSZ, 1024>>>(pdst);
    }

    cudaMemcpyAsync(mfin, mapso + 4*BSZ*FCH*NPIX,
                    (size_t)BSZ*FCH*NPIX*sizeof(float),
                    cudaMemcpyDeviceToDevice);
}

// round 3
// speedup vs baseline: 1.3314x; 1.3314x over previous
#include <cuda_runtime.h>
#include <math.h>

// Problem constants
#define LL    6
#define BSZ   8
#define FCH   32
#define MAPD  125
#define LOCD  25
#define NA    8
#define NPIX  (MAPD*MAPD)   // 15625
#define KSZ   (LOCD*LOCD)   // 625

// Conv tiling: 8 output rows per block (4 row-pairs), halo 24
#define TY    8
#define NYT   16            // ceil(125/8)
#define TROWS 32            // TY + 24
#define TC2   152           // 149 cols padded

#define CONV_SMEM (8*KSZ*4 + TROWS*TC2*8)   // 20000 + 38912 = 58912 B

// Scratch (device globals; no allocation allowed)
__device__ float g_rot[LL*BSZ*NA*FCH*KSZ];     // rotated tiles [l][b][a][f][25][25]
__device__ float g_oreg[BSZ*FCH*NPIX];         // conv1 output (GRU input)
__device__ float g_msm[BSZ*(FCH-1)*NPIX];      // channel-softmaxed maps, ch 1..31
__device__ float g_scoresP[4][BSZ*NA*NPIX];    // conv2 partial outputs (4 channel splits)

// Packed fp32x2 FMA (Blackwell FFMA2 — only reachable via PTX)
#define FMA2(d, a, b) \
    asm("fma.rn.f32x2 %0, %1, %2, %3;" : "=l"(d) : "l"(a), "l"(b), "l"(d))
#define PACK_DUP(d, w) \
    asm("mov.b64 %0, {%1, %1};" : "=l"(d) : "f"(w))
#define UNPACK2(lo, hi, d) \
    asm("mov.b64 {%0, %1}, %2;" : "=f"(lo), "=f"(hi) : "l"(d))

// ---------------------------------------------------------------------------
// Rotation resample: image_cls (L,BS,F,25,25) -> g_rot (L,BS,A,F,25,25)
// ---------------------------------------------------------------------------
__global__ void resample_kernel(const float* __restrict__ img)
{
    int idx = blockIdx.x * blockDim.x + threadIdx.x;
    const int total = LL*BSZ*NA*FCH*KSZ;
    if (idx >= total) return;

    int xx = idx % LOCD;
    int yy = (idx / LOCD) % LOCD;
    int f  = (idx / KSZ) % FCH;
    int a  = (idx / (KSZ*FCH)) % NA;
    int lb = idx / (KSZ*FCH*NA);

    float gx = -1.0f + (float)xx * (2.0f/24.0f);
    float gy = -1.0f + (float)yy * (2.0f/24.0f);
    float ang = (float)a * 0.78539816339744830961f;
    float sn, c;
    sincosf(ang, &sn, &c);
    float px = (c*gx - sn*gy + 1.0f) * 12.0f;
    float py = (sn*gx + c*gy + 1.0f) * 12.0f;

    int x0 = (int)floorf(px);
    int y0 = (int)floorf(py);
    float wx1 = px - (float)x0, wy1 = py - (float)y0;
    float wx0 = 1.0f - wx1,     wy0 = 1.0f - wy1;

    const float* im = img + (lb*FCH + f)*KSZ;
    float v00 = (y0   >= 0 && y0   < LOCD && x0   >= 0 && x0   < LOCD) ? im[y0*LOCD + x0]       : 0.0f;
    float v01 = (y0   >= 0 && y0   < LOCD && x0+1 >= 0 && x0+1 < LOCD) ? im[y0*LOCD + x0+1]     : 0.0f;
    float v10 = (y0+1 >= 0 && y0+1 < LOCD && x0   >= 0 && x0   < LOCD) ? im[(y0+1)*LOCD + x0]   : 0.0f;
    float v11 = (y0+1 >= 0 && y0+1 < LOCD && x0+1 >= 0 && x0+1 < LOCD) ? im[(y0+1)*LOCD + x0+1] : 0.0f;

    g_rot[idx] = v00*wy0*wx0 + v01*wy0*wx1 + v10*wy1*wx0 + v11*wy1*wx1;
}

// ---------------------------------------------------------------------------
// conv1 at t=0: p0 is a delta at (a=0, y=62, x=62) -> just stamp rot[0,b,0,f]
// o_reg[b,f,y,x] = rot[0,b,0,f,y-50,x-50] for y,x in [50,74], else 0.
// ---------------------------------------------------------------------------
__global__ void conv1_t0_kernel()
{
    int idx = blockIdx.x * blockDim.x + threadIdx.x;
    if (idx >= BSZ*FCH*NPIX) return;
    int x  = idx % MAPD;
    int y  = (idx / MAPD) % MAPD;
    int f  = (idx / NPIX) % FCH;
    int b  = idx / (NPIX*FCH);
    float v = 0.0f;
    if (y >= 50 && y <= 74 && x >= 50 && x <= 74)
        v = g_rot[((b*NA + 0)*FCH + f)*KSZ + (y-50)*LOCD + (x-50)];
    g_oreg[idx] = v;
}

// ---------------------------------------------------------------------------
// conv1 (write-memory), t>=1:
// o_reg[b,f,y,x] = sum_{a,j,i} rot[t,b,a,f,j,i] * p[b,a,y+12-j,x+12-i]
// block = (ytile, co-group of 8, b); 128 threads; f32x2 packed row-pairs
// ---------------------------------------------------------------------------
__global__ __launch_bounds__(128)
void conv1_kernel(int t, const float* __restrict__ psrc)
{
    extern __shared__ float smem[];
    float*  wts = smem;                          // 8*625 floats
    float2* pt2 = (float2*)(smem + 8*KSZ);       // [TROWS][TC2] pairs (row r, row r+1)
    const unsigned long long* pt64 = (const unsigned long long*)pt2;

    const int tid = threadIdx.x;
    const int yt  = blockIdx.x;
    const int cg  = blockIdx.y;                  // 0..3
    const int b   = blockIdx.z;
    const int y0  = yt * TY;

    const float* rot_t = g_rot + t * (BSZ*NA*FCH*KSZ);

    unsigned long long acc[4][8];
#pragma unroll
    for (int s = 0; s < 4; s++)
#pragma unroll
        for (int co = 0; co < 8; co++) acc[s][co] = 0ULL;

    for (int a = 0; a < NA; a++) {
        __syncthreads();
        const float* ps = psrc + (b*NA + a)*NPIX;
        for (int i = tid; i < TROWS*TC2; i += 128) {
            int rr = i / TC2, cc = i % TC2;
            int gy = y0 + rr - 12, gx = cc - 12;
            float2 v;
            v.x = (gy   >= 0 && gy   < MAPD && gx >= 0 && gx < MAPD) ? ps[gy*MAPD + gx]     : 0.0f;
            v.y = (gy+1 >= 0 && gy+1 < MAPD && gx >= 0 && gx < MAPD) ? ps[(gy+1)*MAPD + gx] : 0.0f;
            pt2[i] = v;
        }
        const float* ws = rot_t + ((b*NA + a)*FCH + cg*8)*KSZ;
        for (int i = tid; i < 8*KSZ; i += 128) wts[i] = ws[i];
        __syncthreads();

        if (tid < MAPD) {
            for (int j = 0; j < LOCD; j++) {
                const float* wrow = wts + j*LOCD;
                int pidx0 = (24 - j)*TC2 + tid + 24;
#pragma unroll 5
                for (int i = 0; i < LOCD; i++) {
                    unsigned long long pv[4];
#pragma unroll
                    for (int s = 0; s < 4; s++)
                        pv[s] = pt64[pidx0 - i + s*(2*TC2)];
#pragma unroll
                    for (int co = 0; co < 8; co++) {
                        unsigned long long w2;
                        PACK_DUP(w2, wrow[co*KSZ + i]);
#pragma unroll
                        for (int s = 0; s < 4; s++)
                            FMA2(acc[s][co], pv[s], w2);
                    }
                }
            }
        }
    }

    if (tid < MAPD) {
#pragma unroll
        for (int co = 0; co < 8; co++)
#pragma unroll
            for (int s = 0; s < 4; s++) {
                float lo, hi;
                UNPACK2(lo, hi, acc[s][co]);
                int y = y0 + 2*s;
                float* dst = g_oreg + (b*FCH + cg*8 + co)*NPIX + y*MAPD + tid;
                if (y   < MAPD) dst[0]    = lo;
                if (y+1 < MAPD) dst[MAPD] = hi;
            }
    }
}

// ---------------------------------------------------------------------------
// GRU cell per pixel + channel softmax.
// ---------------------------------------------------------------------------
__global__ __launch_bounds__(128)
void gru_kernel(const float* __restrict__ hprev,
                const float* __restrict__ w_ih, const float* __restrict__ w_hh,
                const float* __restrict__ b_ih, const float* __restrict__ b_hh,
                float* __restrict__ mout)
{
    __shared__ float4 s_wih[96*8];
    __shared__ float4 s_whh[96*8];
    __shared__ float  s_b[192];

    const int tid = threadIdx.x;
    const float4* wi4 = (const float4*)w_ih;
    const float4* wh4 = (const float4*)w_hh;
    for (int i = tid; i < 96*8; i += 128) { s_wih[i] = wi4[i]; s_whh[i] = wh4[i]; }
    if (tid < 96) { s_b[tid] = b_ih[tid]; s_b[96+tid] = b_hh[tid]; }
    __syncthreads();

    const int pix = blockIdx.x * 128 + tid;
    if (pix >= NPIX) return;
    const int b = blockIdx.y;

    float x[32], h[32];
#pragma unroll
    for (int c = 0; c < 32; c++) {
        x[c] = g_oreg[(b*FCH + c)*NPIX + pix];
        h[c] = hprev[(b*FCH + c)*NPIX + pix];
    }

    float mx = -1e30f;
    float mvals[32];
    for (int c = 0; c < 32; c++) {
        float accr = s_b[c]      + s_b[96+c];
        float accz = s_b[32+c]   + s_b[128+c];
        float acci = s_b[64+c];
        float acch = s_b[160+c];
        const float4* wr_i = s_wih + c*8;
        const float4* wz_i = s_wih + (32+c)*8;
        const float4* wn_i = s_wih + (64+c)*8;
        const float4* wr_h = s_whh + c*8;
        const float4* wz_h = s_whh + (32+c)*8;
        const float4* wn_h = s_whh + (64+c)*8;
#pragma unroll
        for (int k = 0; k < 8; k++) {
            float4 wv;
            wv = wr_i[k]; accr += wv.x*x[4*k] + wv.y*x[4*k+1] + wv.z*x[4*k+2] + wv.w*x[4*k+3];
            wv = wr_h[k]; accr += wv.x*h[4*k] + wv.y*h[4*k+1] + wv.z*h[4*k+2] + wv.w*h[4*k+3];
            wv = wz_i[k]; accz += wv.x*x[4*k] + wv.y*x[4*k+1] + wv.z*x[4*k+2] + wv.w*x[4*k+3];
            wv = wz_h[k]; accz += wv.x*h[4*k] + wv.y*h[4*k+1] + wv.z*h[4*k+2] + wv.w*h[4*k+3];
            wv = wn_i[k]; acci += wv.x*x[4*k] + wv.y*x[4*k+1] + wv.z*x[4*k+2] + wv.w*x[4*k+3];
            wv = wn_h[k]; acch += wv.x*h[4*k] + wv.y*h[4*k+1] + wv.z*h[4*k+2] + wv.w*h[4*k+3];
        }
        float r = 1.0f/(1.0f + expf(-accr));
        float z = 1.0f/(1.0f + expf(-accz));
        float n = tanhf(acci + r*acch);
        float mv = (1.0f - z)*n + z*h[c];
        mvals[c] = mv;
        mout[(b*FCH + c)*NPIX + pix] = mv;
        mx = fmaxf(mx, mv);
    }

    float sum = 0.0f;
    float e[32];
#pragma unroll
    for (int c = 0; c < 32; c++) { e[c] = expf(mvals[c] - mx); sum += e[c]; }
    float inv = 1.0f / sum;
#pragma unroll
    for (int c = 1; c < 32; c++)
        g_msm[(b*(FCH-1) + (c-1))*NPIX + pix] = e[c] * inv;
}

// ---------------------------------------------------------------------------
// conv2 (localize): scores[b,a,y,x] = sum_{c,ky,kx}
//    msm[b,c,y+ky-12,x+kx-12] * rot[t+1,b,a,c+1,ky,kx]
// block = (ytile, channel-split q, b); partial sums into g_scoresP[q]
// ---------------------------------------------------------------------------
__global__ __launch_bounds__(128)
void conv2_kernel(int t)
{
    extern __shared__ float smem[];
    float*  wts = smem;                          // 8*625
    float2* pt2 = (float2*)(smem + 8*KSZ);
    const unsigned long long* pt64 = (const unsigned long long*)pt2;

    const int tid = threadIdx.x;
    const int yt  = blockIdx.x;
    const int q   = blockIdx.y;                  // 0..3
    const int b   = blockIdx.z;
    const int y0  = yt * TY;
    const int c0  = q * 8;
    int c1 = c0 + 8;
    if (c1 > FCH-1) c1 = FCH-1;

    const float* rot_n = g_rot + (t+1) * (BSZ*NA*FCH*KSZ);

    unsigned long long acc[4][8];
#pragma unroll
    for (int s = 0; s < 4; s++)
#pragma unroll
        for (int a = 0; a < 8; a++) acc[s][a] = 0ULL;

    for (int c = c0; c < c1; c++) {
        __syncthreads();
        const float* ps = g_msm + (b*(FCH-1) + c)*NPIX;
        for (int i = tid; i < TROWS*TC2; i += 128) {
            int rr = i / TC2, cc = i % TC2;
            int gy = y0 + rr - 12, gx = cc - 12;
            float2 v;
            v.x = (gy   >= 0 && gy   < MAPD && gx >= 0 && gx < MAPD) ? ps[gy*MAPD + gx]     : 0.0f;
            v.y = (gy+1 >= 0 && gy+1 < MAPD && gx >= 0 && gx < MAPD) ? ps[(gy+1)*MAPD + gx] : 0.0f;
            pt2[i] = v;
        }
        for (int i = tid; i < 8*KSZ; i += 128) {
            int a = i / KSZ, k = i % KSZ;
            wts[i] = rot_n[((b*NA + a)*FCH + (c+1))*KSZ + k];
        }
        __syncthreads();

        if (tid < MAPD) {
            for (int ky = 0; ky < LOCD; ky++) {
                const float* wrow = wts + ky*LOCD;
                int pidx0 = ky*TC2 + tid;
#pragma unroll 5
                for (int kx = 0; kx < LOCD; kx++) {
                    unsigned long long pv[4];
#pragma unroll
                    for (int s = 0; s < 4; s++)
                        pv[s] = pt64[pidx0 + kx + s*(2*TC2)];
#pragma unroll
                    for (int a = 0; a < 8; a++) {
                        unsigned long long w2;
                        PACK_DUP(w2, wrow[a*KSZ + kx]);
#pragma unroll
                        for (int s = 0; s < 4; s++)
                            FMA2(acc[s][a], pv[s], w2);
                    }
                }
            }
        }
    }

    if (tid < MAPD) {
#pragma unroll
        for (int a = 0; a < 8; a++)
#pragma unroll
            for (int s = 0; s < 4; s++) {
                float lo, hi;
                UNPACK2(lo, hi, acc[s][a]);
                int y = y0 + 2*s;
                float* dst = g_scoresP[q] + (b*NA + a)*NPIX + y*MAPD + tid;
                if (y   < MAPD) dst[0]    = lo;
                if (y+1 < MAPD) dst[MAPD] = hi;
            }
    }
}

// ---------------------------------------------------------------------------
// Global softmax over (A,H,W), summing the 4 conv2 partials.
// ---------------------------------------------------------------------------
__global__ void softmax_pose_kernel(float* __restrict__ pdst)
{
    const int b = blockIdx.x;
    const int base = b*NA*NPIX;
    float* o = pdst + base;
    const int N = NA*NPIX;
    __shared__ float red[33];
    const int tid = threadIdx.x;

    float mx = -1e30f;
    for (int i = tid; i < N; i += 1024) {
        float s = g_scoresP[0][base+i] + g_scoresP[1][base+i]
                + g_scoresP[2][base+i] + g_scoresP[3][base+i];
        mx = fmaxf(mx, s);
    }
#pragma unroll
    for (int off = 16; off; off >>= 1) mx = fmaxf(mx, __shfl_xor_sync(0xffffffffu, mx, off));
    if ((tid & 31) == 0) red[tid >> 5] = mx;
    __syncthreads();
    if (tid < 32) {
        float v = red[tid];
#pragma unroll
        for (int off = 16; off; off >>= 1) v = fmaxf(v, __shfl_xor_sync(0xffffffffu, v, off));
        if (tid == 0) red[32] = v;
    }
    __syncthreads();
    mx = red[32];
    __syncthreads();

    float sum = 0.0f;
    for (int i = tid; i < N; i += 1024) {
        float s = g_scoresP[0][base+i] + g_scoresP[1][base+i]
                + g_scoresP[2][base+i] + g_scoresP[3][base+i];
        sum += expf(s - mx);
    }
#pragma unroll
    for (int off = 16; off; off >>= 1) sum += __shfl_xor_sync(0xffffffffu, sum, off);
    if ((tid & 31) == 0) red[tid >> 5] = sum;
    __syncthreads();
    if (tid < 32) {
        float v = red[tid];
#pragma unroll
        for (int off = 16; off; off >>= 1) v += __shfl_xor_sync(0xffffffffu, v, off);
        if (tid == 0) red[32] = v;
    }
    __syncthreads();
    float inv = 1.0f / red[32];

    for (int i = tid; i < N; i += 1024) {
        float s = g_scoresP[0][base+i] + g_scoresP[1][base+i]
                + g_scoresP[2][base+i] + g_scoresP[3][base+i];
        o[i] = expf(s - mx) * inv;
    }
}

// ---------------------------------------------------------------------------
// Host launcher (graph-capturable, allocation-free).
// Output: poses_all (5,8,8,125,125) | maps_all (5,8,32,125,125) | m_final (8,32,125,125)
// ---------------------------------------------------------------------------
extern "C" void kernel_launch(void* const* d_in, const int* in_sizes, int n_in,
                              void* d_out, int out_size)
{
    const float* img   = (const float*)d_in[0];
    const float* maps0 = (const float*)d_in[1];
    const float* w_ih  = (const float*)d_in[3];
    const float* w_hh  = (const float*)d_in[4];
    const float* b_ih  = (const float*)d_in[5];
    const float* b_hh  = (const float*)d_in[6];

    float* out   = (float*)d_out;
    float* poses = out;
    float* mapso = out + 5*BSZ*NA*NPIX;
    float* mfin  = out + 5*BSZ*NA*NPIX + 5*BSZ*FCH*NPIX;

    cudaFuncSetAttribute(conv1_kernel, cudaFuncAttributeMaxDynamicSharedMemorySize, CONV_SMEM);
    cudaFuncSetAttribute(conv2_kernel, cudaFuncAttributeMaxDynamicSharedMemorySize, CONV_SMEM);

    resample_kernel<<<(LL*BSZ*NA*FCH*KSZ + 255)/256, 256>>>(img);

    for (int t = 0; t < LL-1; t++) {
        const float* hsrc = (t == 0) ? maps0 : (mapso + (t-1)*BSZ*FCH*NPIX);
        float* mdst = mapso + t*BSZ*FCH*NPIX;
        float* pdst = poses + t*BSZ*NA*NPIX;

        if (t == 0) {
            conv1_t0_kernel<<<(BSZ*FCH*NPIX + 255)/256, 256>>>();
        } else {
            const float* psrc = poses + (t-1)*BSZ*NA*NPIX;
            conv1_kernel<<<dim3(NYT, 4, BSZ), 128, CONV_SMEM>>>(t, psrc);
        }
        gru_kernel<<<dim3((NPIX + 127)/128, BSZ), 128>>>(hsrc, w_ih, w_hh, b_ih, b_hh, mdst);
        conv2_kernel<<<dim3(NYT, 4, BSZ), 128, CONV_SMEM>>>(t);
        softmax_pose_kernel<<<BSZ, 1024>>>(pdst);
    }

    cudaMemcpyAsync(mfin, mapso + 4*BSZ*FCH*NPIX,
                    (size_t)BSZ*FCH*NPIX*sizeof(float),
                    cudaMemcpyDeviceToDevice);
}

// round 4
// speedup vs baseline: 1.3763x; 1.0337x over previous
#include <cuda_runtime.h>
#include <math.h>

// Problem constants
#define LL    6
#define BSZ   8
#define FCH   32
#define MAPD  125
#define LOCD  25
#define NA    8
#define NPIX  (MAPD*MAPD)   // 15625
#define KSZ   (LOCD*LOCD)   // 625

// Conv tiling: 16 output rows per block (two warp-groups x 4 row-pairs), halo 24
#define TYB   16            // rows per block
#define NYT   8             // ceil(125/16)
#define TROWS 40            // TYB + 24
#define TC2   152           // 149 cols padded

#define CONV_SMEM (8*KSZ*4 + TROWS*TC2*8)   // 20000 + 48640 = 68640 B

// Scratch (device globals; no allocation allowed)
__device__ float g_rot[LL*BSZ*NA*FCH*KSZ];     // rotated tiles [l][b][a][f][25][25]
__device__ float g_oreg[BSZ*FCH*NPIX];         // conv1 output (GRU input)
__device__ float g_msm[BSZ*(FCH-1)*NPIX];      // channel-softmaxed maps, ch 1..31
__device__ float g_scoresP[4][BSZ*NA*NPIX];    // conv2 partial outputs (4 channel splits)

// Packed fp32x2 FMA (Blackwell FFMA2 — only reachable via PTX)
#define FMA2(d, a, b) \
    asm("fma.rn.f32x2 %0, %1, %2, %3;" : "=l"(d) : "l"(a), "l"(b), "l"(d))
#define PACK_DUP(d, w) \
    asm("mov.b64 %0, {%1, %1};" : "=l"(d) : "f"(w))
#define UNPACK2(lo, hi, d) \
    asm("mov.b64 {%0, %1}, %2;" : "=f"(lo), "=f"(hi) : "l"(d))

// ---------------------------------------------------------------------------
// Rotation resample: image_cls (L,BS,F,25,25) -> g_rot (L,BS,A,F,25,25)
// ---------------------------------------------------------------------------
__global__ void resample_kernel(const float* __restrict__ img)
{
    int idx = blockIdx.x * blockDim.x + threadIdx.x;
    const int total = LL*BSZ*NA*FCH*KSZ;
    if (idx >= total) return;

    int xx = idx % LOCD;
    int yy = (idx / LOCD) % LOCD;
    int f  = (idx / KSZ) % FCH;
    int a  = (idx / (KSZ*FCH)) % NA;
    int lb = idx / (KSZ*FCH*NA);

    float gx = -1.0f + (float)xx * (2.0f/24.0f);
    float gy = -1.0f + (float)yy * (2.0f/24.0f);
    float ang = (float)a * 0.78539816339744830961f;
    float sn, c;
    sincosf(ang, &sn, &c);
    float px = (c*gx - sn*gy + 1.0f) * 12.0f;
    float py = (sn*gx + c*gy + 1.0f) * 12.0f;

    int x0 = (int)floorf(px);
    int y0 = (int)floorf(py);
    float wx1 = px - (float)x0, wy1 = py - (float)y0;
    float wx0 = 1.0f - wx1,     wy0 = 1.0f - wy1;

    const float* im = img + (lb*FCH + f)*KSZ;
    float v00 = (y0   >= 0 && y0   < LOCD && x0   >= 0 && x0   < LOCD) ? im[y0*LOCD + x0]       : 0.0f;
    float v01 = (y0   >= 0 && y0   < LOCD && x0+1 >= 0 && x0+1 < LOCD) ? im[y0*LOCD + x0+1]     : 0.0f;
    float v10 = (y0+1 >= 0 && y0+1 < LOCD && x0   >= 0 && x0   < LOCD) ? im[(y0+1)*LOCD + x0]   : 0.0f;
    float v11 = (y0+1 >= 0 && y0+1 < LOCD && x0+1 >= 0 && x0+1 < LOCD) ? im[(y0+1)*LOCD + x0+1] : 0.0f;

    g_rot[idx] = v00*wy0*wx0 + v01*wy0*wx1 + v10*wy1*wx0 + v11*wy1*wx1;
}

// ---------------------------------------------------------------------------
// conv1 at t=0: p0 is a delta at (a=0, y=62, x=62) -> just stamp rot[0,b,0,f]
// ---------------------------------------------------------------------------
__global__ void conv1_t0_kernel()
{
    int idx = blockIdx.x * blockDim.x + threadIdx.x;
    if (idx >= BSZ*FCH*NPIX) return;
    int x  = idx % MAPD;
    int y  = (idx / MAPD) % MAPD;
    int f  = (idx / NPIX) % FCH;
    int b  = idx / (NPIX*FCH);
    float v = 0.0f;
    if (y >= 50 && y <= 74 && x >= 50 && x <= 74)
        v = g_rot[((b*NA + 0)*FCH + f)*KSZ + (y-50)*LOCD + (x-50)];
    g_oreg[idx] = v;
}

// ---------------------------------------------------------------------------
// conv1 (write-memory), t>=1:
// o_reg[b,f,y,x] = sum_{a,j,i} rot[t,b,a,f,j,i] * p[b,a,y+12-j,x+12-i]
// block = (ytile16, co-group of 8, b); 256 threads (2 warp-groups share tile+wts)
// ---------------------------------------------------------------------------
__global__ __launch_bounds__(256)
void conv1_kernel(int t, const float* __restrict__ psrc)
{
    extern __shared__ float smem[];
    float*  wts = smem;                          // 8*625 floats
    float2* pt2 = (float2*)(smem + 8*KSZ);       // [TROWS][TC2] pairs (row r, row r+1)
    const unsigned long long* pt64 = (const unsigned long long*)pt2;

    const int tid = threadIdx.x;
    const int wg  = tid >> 7;                    // warp-group 0/1
    const int wt  = tid & 127;
    const int yt  = blockIdx.x;
    const int cg  = blockIdx.y;                  // 0..3
    const int b   = blockIdx.z;
    const int y0  = yt * TYB;

    const float* rot_t = g_rot + t * (BSZ*NA*FCH*KSZ);

    unsigned long long acc[4][8];
#pragma unroll
    for (int s = 0; s < 4; s++)
#pragma unroll
        for (int co = 0; co < 8; co++) acc[s][co] = 0ULL;

    for (int a = 0; a < NA; a++) {
        __syncthreads();
        const float* ps = psrc + (b*NA + a)*NPIX;
        for (int i = tid; i < TROWS*TC2; i += 256) {
            int rr = i / TC2, cc = i % TC2;
            int gy = y0 + rr - 12, gx = cc - 12;
            float2 v;
            v.x = (gy   >= 0 && gy   < MAPD && gx >= 0 && gx < MAPD) ? ps[gy*MAPD + gx]     : 0.0f;
            v.y = (gy+1 >= 0 && gy+1 < MAPD && gx >= 0 && gx < MAPD) ? ps[(gy+1)*MAPD + gx] : 0.0f;
            pt2[i] = v;
        }
        const float* ws = rot_t + ((b*NA + a)*FCH + cg*8)*KSZ;
        for (int i = tid; i < 8*KSZ; i += 256) wts[i] = ws[i];
        __syncthreads();

        if (wt < MAPD) {
            for (int j = 0; j < LOCD; j++) {
                const float* wrow = wts + j*LOCD;
                int pidx0 = (24 - j + wg*8)*TC2 + wt + 24;
#pragma unroll 5
                for (int i = 0; i < LOCD; i++) {
                    unsigned long long pv[4];
#pragma unroll
                    for (int s = 0; s < 4; s++)
                        pv[s] = pt64[pidx0 - i + s*(2*TC2)];
#pragma unroll
                    for (int co = 0; co < 8; co++) {
                        unsigned long long w2;
                        PACK_DUP(w2, wrow[co*KSZ + i]);
#pragma unroll
                        for (int s = 0; s < 4; s++)
                            FMA2(acc[s][co], pv[s], w2);
                    }
                }
            }
        }
    }

    if (wt < MAPD) {
#pragma unroll
        for (int co = 0; co < 8; co++)
#pragma unroll
            for (int s = 0; s < 4; s++) {
                float lo, hi;
                UNPACK2(lo, hi, acc[s][co]);
                int y = y0 + wg*8 + 2*s;
                float* dst = g_oreg + (b*FCH + cg*8 + co)*NPIX + y*MAPD + wt;
                if (y   < MAPD) dst[0]    = lo;
                if (y+1 < MAPD) dst[MAPD] = hi;
            }
    }
}

// ---------------------------------------------------------------------------
// GRU cell per pixel + channel softmax.
// ---------------------------------------------------------------------------
__global__ __launch_bounds__(128)
void gru_kernel(const float* __restrict__ hprev,
                const float* __restrict__ w_ih, const float* __restrict__ w_hh,
                const float* __restrict__ b_ih, const float* __restrict__ b_hh,
                float* __restrict__ mout)
{
    __shared__ float4 s_wih[96*8];
    __shared__ float4 s_whh[96*8];
    __shared__ float  s_b[192];

    const int tid = threadIdx.x;
    const float4* wi4 = (const float4*)w_ih;
    const float4* wh4 = (const float4*)w_hh;
    for (int i = tid; i < 96*8; i += 128) { s_wih[i] = wi4[i]; s_whh[i] = wh4[i]; }
    if (tid < 96) { s_b[tid] = b_ih[tid]; s_b[96+tid] = b_hh[tid]; }
    __syncthreads();

    const int pix = blockIdx.x * 128 + tid;
    if (pix >= NPIX) return;
    const int b = blockIdx.y;

    float x[32], h[32];
#pragma unroll
    for (int c = 0; c < 32; c++) {
        x[c] = g_oreg[(b*FCH + c)*NPIX + pix];
        h[c] = hprev[(b*FCH + c)*NPIX + pix];
    }

    float mx = -1e30f;
    float mvals[32];
    for (int c = 0; c < 32; c++) {
        float accr = s_b[c]      + s_b[96+c];
        float accz = s_b[32+c]   + s_b[128+c];
        float acci = s_b[64+c];
        float acch = s_b[160+c];
        const float4* wr_i = s_wih + c*8;
        const float4* wz_i = s_wih + (32+c)*8;
        const float4* wn_i = s_wih + (64+c)*8;
        const float4* wr_h = s_whh + c*8;
        const float4* wz_h = s_whh + (32+c)*8;
        const float4* wn_h = s_whh + (64+c)*8;
#pragma unroll
        for (int k = 0; k < 8; k++) {
            float4 wv;
            wv = wr_i[k]; accr += wv.x*x[4*k] + wv.y*x[4*k+1] + wv.z*x[4*k+2] + wv.w*x[4*k+3];
            wv = wr_h[k]; accr += wv.x*h[4*k] + wv.y*h[4*k+1] + wv.z*h[4*k+2] + wv.w*h[4*k+3];
            wv = wz_i[k]; accz += wv.x*x[4*k] + wv.y*x[4*k+1] + wv.z*x[4*k+2] + wv.w*x[4*k+3];
            wv = wz_h[k]; accz += wv.x*h[4*k] + wv.y*h[4*k+1] + wv.z*h[4*k+2] + wv.w*h[4*k+3];
            wv = wn_i[k]; acci += wv.x*x[4*k] + wv.y*x[4*k+1] + wv.z*x[4*k+2] + wv.w*x[4*k+3];
            wv = wn_h[k]; acch += wv.x*h[4*k] + wv.y*h[4*k+1] + wv.z*h[4*k+2] + wv.w*h[4*k+3];
        }
        float r = 1.0f/(1.0f + expf(-accr));
        float z = 1.0f/(1.0f + expf(-accz));
        float n = tanhf(acci + r*acch);
        float mv = (1.0f - z)*n + z*h[c];
        mvals[c] = mv;
        mout[(b*FCH + c)*NPIX + pix] = mv;
        mx = fmaxf(mx, mv);
    }

    float sum = 0.0f;
    float e[32];
#pragma unroll
    for (int c = 0; c < 32; c++) { e[c] = expf(mvals[c] - mx); sum += e[c]; }
    float inv = 1.0f / sum;
#pragma unroll
    for (int c = 1; c < 32; c++)
        g_msm[(b*(FCH-1) + (c-1))*NPIX + pix] = e[c] * inv;
}

// ---------------------------------------------------------------------------
// conv2 (localize): scores[b,a,y,x] = sum_{c,ky,kx}
//    msm[b,c,y+ky-12,x+kx-12] * rot[t+1,b,a,c+1,ky,kx]
// block = (ytile16, channel-split q, b); 256 threads (2 warp-groups share tile+wts)
// ---------------------------------------------------------------------------
__global__ __launch_bounds__(256)
void conv2_kernel(int t)
{
    extern __shared__ float smem[];
    float*  wts = smem;                          // 8*625
    float2* pt2 = (float2*)(smem + 8*KSZ);
    const unsigned long long* pt64 = (const unsigned long long*)pt2;

    const int tid = threadIdx.x;
    const int wg  = tid >> 7;
    const int wt  = tid & 127;
    const int yt  = blockIdx.x;
    const int q   = blockIdx.y;                  // 0..3
    const int b   = blockIdx.z;
    const int y0  = yt * TYB;
    const int c0  = q * 8;
    int c1 = c0 + 8;
    if (c1 > FCH-1) c1 = FCH-1;

    const float* rot_n = g_rot + (t+1) * (BSZ*NA*FCH*KSZ);

    unsigned long long acc[4][8];
#pragma unroll
    for (int s = 0; s < 4; s++)
#pragma unroll
        for (int a = 0; a < 8; a++) acc[s][a] = 0ULL;

    for (int c = c0; c < c1; c++) {
        __syncthreads();
        const float* ps = g_msm + (b*(FCH-1) + c)*NPIX;
        for (int i = tid; i < TROWS*TC2; i += 256) {
            int rr = i / TC2, cc = i % TC2;
            int gy = y0 + rr - 12, gx = cc - 12;
            float2 v;
            v.x = (gy   >= 0 && gy   < MAPD && gx >= 0 && gx < MAPD) ? ps[gy*MAPD + gx]     : 0.0f;
            v.y = (gy+1 >= 0 && gy+1 < MAPD && gx >= 0 && gx < MAPD) ? ps[(gy+1)*MAPD + gx] : 0.0f;
            pt2[i] = v;
        }
        for (int i = tid; i < 8*KSZ; i += 256) {
            int a = i / KSZ, k = i % KSZ;
            wts[i] = rot_n[((b*NA + a)*FCH + (c+1))*KSZ + k];
        }
        __syncthreads();

        if (wt < MAPD) {
            for (int ky = 0; ky < LOCD; ky++) {
                const float* wrow = wts + ky*LOCD;
                int pidx0 = (ky + wg*8)*TC2 + wt;
#pragma unroll 5
                for (int kx = 0; kx < LOCD; kx++) {
                    unsigned long long pv[4];
#pragma unroll
                    for (int s = 0; s < 4; s++)
                        pv[s] = pt64[pidx0 + kx + s*(2*TC2)];
#pragma unroll
                    for (int a = 0; a < 8; a++) {
                        unsigned long long w2;
                        PACK_DUP(w2, wrow[a*KSZ + kx]);
#pragma unroll
                        for (int s = 0; s < 4; s++)
                            FMA2(acc[s][a], pv[s], w2);
                    }
                }
            }
        }
    }

    if (wt < MAPD) {
#pragma unroll
        for (int a = 0; a < 8; a++)
#pragma unroll
            for (int s = 0; s < 4; s++) {
                float lo, hi;
                UNPACK2(lo, hi, acc[s][a]);
                int y = y0 + wg*8 + 2*s;
                float* dst = g_scoresP[q] + (b*NA + a)*NPIX + y*MAPD + wt;
                if (y   < MAPD) dst[0]    = lo;
                if (y+1 < MAPD) dst[MAPD] = hi;
            }
    }
}

// ---------------------------------------------------------------------------
// Global softmax over (A,H,W), summing the 4 conv2 partials.
// ---------------------------------------------------------------------------
__global__ void softmax_pose_kernel(float* __restrict__ pdst)
{
    const int b = blockIdx.x;
    const int base = b*NA*NPIX;
    float* o = pdst + base;
    const int N = NA*NPIX;
    __shared__ float red[33];
    const int tid = threadIdx.x;

    float mx = -1e30f;
    for (int i = tid; i < N; i += 1024) {
        float s = g_scoresP[0][base+i] + g_scoresP[1][base+i]
                + g_scoresP[2][base+i] + g_scoresP[3][base+i];
        mx = fmaxf(mx, s);
    }
#pragma unroll
    for (int off = 16; off; off >>= 1) mx = fmaxf(mx, __shfl_xor_sync(0xffffffffu, mx, off));
    if ((tid & 31) == 0) red[tid >> 5] = mx;
    __syncthreads();
    if (tid < 32) {
        float v = red[tid];
#pragma unroll
        for (int off = 16; off; off >>= 1) v = fmaxf(v, __shfl_xor_sync(0xffffffffu, v, off));
        if (tid == 0) red[32] = v;
    }
    __syncthreads();
    mx = red[32];
    __syncthreads();

    float sum = 0.0f;
    for (int i = tid; i < N; i += 1024) {
        float s = g_scoresP[0][base+i] + g_scoresP[1][base+i]
                + g_scoresP[2][base+i] + g_scoresP[3][base+i];
        sum += expf(s - mx);
    }
#pragma unroll
    for (int off = 16; off; off >>= 1) sum += __shfl_xor_sync(0xffffffffu, sum, off);
    if ((tid & 31) == 0) red[tid >> 5] = sum;
    __syncthreads();
    if (tid < 32) {
        float v = red[tid];
#pragma unroll
        for (int off = 16; off; off >>= 1) v += __shfl_xor_sync(0xffffffffu, v, off);
        if (tid == 0) red[32] = v;
    }
    __syncthreads();
    float inv = 1.0f / red[32];

    for (int i = tid; i < N; i += 1024) {
        float s = g_scoresP[0][base+i] + g_scoresP[1][base+i]
                + g_scoresP[2][base+i] + g_scoresP[3][base+i];
        o[i] = expf(s - mx) * inv;
    }
}

// ---------------------------------------------------------------------------
// Host launcher (graph-capturable, allocation-free).
// Output: poses_all (5,8,8,125,125) | maps_all (5,8,32,125,125) | m_final (8,32,125,125)
// ---------------------------------------------------------------------------
extern "C" void kernel_launch(void* const* d_in, const int* in_sizes, int n_in,
                              void* d_out, int out_size)
{
    const float* img   = (const float*)d_in[0];
    const float* maps0 = (const float*)d_in[1];
    const float* w_ih  = (const float*)d_in[3];
    const float* w_hh  = (const float*)d_in[4];
    const float* b_ih  = (const float*)d_in[5];
    const float* b_hh  = (const float*)d_in[6];

    float* out   = (float*)d_out;
    float* poses = out;
    float* mapso = out + 5*BSZ*NA*NPIX;
    float* mfin  = out + 5*BSZ*NA*NPIX + 5*BSZ*FCH*NPIX;

    cudaFuncSetAttribute(conv1_kernel, cudaFuncAttributeMaxDynamicSharedMemorySize, CONV_SMEM);
    cudaFuncSetAttribute(conv2_kernel, cudaFuncAttributeMaxDynamicSharedMemorySize, CONV_SMEM);

    resample_kernel<<<(LL*BSZ*NA*FCH*KSZ + 255)/256, 256>>>(img);

    for (int t = 0; t < LL-1; t++) {
        const float* hsrc = (t == 0) ? maps0 : (mapso + (t-1)*BSZ*FCH*NPIX);
        float* mdst = mapso + t*BSZ*FCH*NPIX;
        float* pdst = poses + t*BSZ*NA*NPIX;

        if (t == 0) {
            conv1_t0_kernel<<<(BSZ*FCH*NPIX + 255)/256, 256>>>();
        } else {
            const float* psrc = poses + (t-1)*BSZ*NA*NPIX;
            conv1_kernel<<<dim3(NYT, 4, BSZ), 256, CONV_SMEM>>>(t, psrc);
        }
        gru_kernel<<<dim3((NPIX + 127)/128, BSZ), 128>>>(hsrc, w_ih, w_hh, b_ih, b_hh, mdst);
        conv2_kernel<<<dim3(NYT, 4, BSZ), 256, CONV_SMEM>>>(t);
        softmax_pose_kernel<<<BSZ, 1024>>>(pdst);
    }

    cudaMemcpyAsync(mfin, mapso + 4*BSZ*FCH*NPIX,
                    (size_t)BSZ*FCH*NPIX*sizeof(float),
                    cudaMemcpyDeviceToDevice);
}